// round 10
// baseline (speedup 1.0000x reference)
#include <cuda_runtime.h>
#include <cuda_bf16.h>
#include <cstdint>
#include <math.h>

// ---------------- problem constants ----------------
#define D_MODEL   1024
#define NUM_TILES 64
#define TPC       8
#define NUM_CL    8
#define COMP_H    256
#define GRIDW     16
#define EPS_LN    1e-5f

// ---------------- GEMM config ----------------
#define NCOL_PAD  352              // 44 n8-tiles (256 hidden + 8 cluster + 64 tile + pad)
#define M_BLK     32
#define KC        32
#define NCHUNK    (D_MODEL / KC)   // 32
#define ROWB      80               // 64B k-data + 16B pad; ldmatrix conflict-free (5 mod 8 walk)
#define CSTRIDE   (NCOL_PAD + 4)   // 356
#define NTHREADS  256
#define NT_PER    11               // n8-tiles per warp (4 n-warps)

#define A_BYTES      (M_BLK * ROWB)           // 2560
#define B_BYTES      (NCOL_PAD * ROWB)        // 28160
#define STAGE_BYTES  (A_BYTES + B_BYTES)      // 30720
#define B_SEGS       (NCOL_PAD * 4)           // 1408 (16B segs per chunk)
#define PARAM_OFF    (2 * STAGE_BYTES)        // 61440 (Csm 45568 aliases stages)
#define SMEM_TOTAL   (PARAM_OFF + 3 * COMP_H * 4)   // 64512

// Wcat, chunk-major: [chunk][row n][k within chunk]
__device__ __nv_bfloat16 g_Wcat[NCHUNK][NCOL_PAD][KC];

// ---------------- prep A: W1 region, float4 tiled transpose ----------------
// grid 32: block b handles k rows [32b, 32b+32) x all 256 n  (exactly chunk b)
__global__ void prep_w1(const float* __restrict__ w1) {
    __shared__ float4 t[32][65];              // [k_local][float4 col], pad avoids conflicts
    const int k0 = blockIdx.x * 32;
    const int s = threadIdx.x;                // 256 threads
    #pragma unroll
    for (int r = 0; r < 8; ++r) {
        int idx = s + r * 256;                // 0..2047 float4 slots
        int kl = idx >> 6, q = idx & 63;
        t[kl][q] = ((const float4*)w1)[(size_t)(k0 + kl) * (COMP_H / 4) + q];
    }
    __syncthreads();
    // thread s = output column n; writes 32 contiguous bf16 (64B) to g_Wcat[b][n][:]
    uint32_t packed[16];
    #pragma unroll
    for (int kl = 0; kl < 16; ++kl) {
        float a = ((const float*)&t[2 * kl][0])[s];
        float b = ((const float*)&t[2 * kl + 1][0])[s];
        __nv_bfloat162 p = __floats2bfloat162_rn(a, b);
        packed[kl] = *reinterpret_cast<uint32_t*>(&p);
    }
    uint4* dst = (uint4*)&g_Wcat[blockIdx.x][s][0];
    #pragma unroll
    for (int j = 0; j < 4; ++j)
        dst[j] = make_uint4(packed[4 * j], packed[4 * j + 1], packed[4 * j + 2], packed[4 * j + 3]);
}

// ---------------- prep B: cluster/tile signatures + pad (k-fastest) ----------
__global__ void prep_sig(const float* __restrict__ raw) {
    int idx = blockIdx.x * blockDim.x + threadIdx.x;     // 96*1024
    if (idx >= (NCOL_PAD - COMP_H) * D_MODEL) return;
    int nn = idx >> 10;            // 0..95
    int k  = idx & 1023;
    int n  = COMP_H + nn;
    float val;
    if (nn < NUM_CL) {
        float s = 0.f;
        #pragma unroll
        for (int j = 0; j < TPC; ++j) {
            float rv = raw[(nn * TPC + j) * D_MODEL + k];
            s += (rv > 0.3f) ? 1.f : ((rv < -0.3f) ? -1.f : 0.f);
        }
        val = (s > 0.f) ? 1.f : ((s < 0.f) ? -1.f : 0.f);
    } else if (nn < NUM_CL + NUM_TILES) {
        float rv = raw[(nn - NUM_CL) * D_MODEL + k];
        val = (rv > 0.3f) ? 1.f : ((rv < -0.3f) ? -1.f : 0.f);
    } else {
        val = 0.f;
    }
    g_Wcat[k >> 5][n][k & 31] = __float2bfloat16(val);
}

// ---------------- helpers ----------------
__device__ __forceinline__ float gelu_exact(float v) {
    return 0.5f * v * (1.0f + erff(v * 0.7071067811865476f));
}
__device__ __forceinline__ void mma16816(float c[4], uint32_t a0, uint32_t a1,
                                         uint32_t a2, uint32_t a3,
                                         uint32_t b0, uint32_t b1) {
    asm volatile(
        "mma.sync.aligned.m16n8k16.row.col.f32.bf16.bf16.f32 "
        "{%0,%1,%2,%3}, {%4,%5,%6,%7}, {%8,%9}, {%0,%1,%2,%3};\n"
        : "+f"(c[0]), "+f"(c[1]), "+f"(c[2]), "+f"(c[3])
        : "r"(a0), "r"(a1), "r"(a2), "r"(a3), "r"(b0), "r"(b1));
}
__device__ __forceinline__ void ldsm_x4(uint32_t& r0, uint32_t& r1, uint32_t& r2,
                                        uint32_t& r3, uint32_t addr) {
    asm volatile("ldmatrix.sync.aligned.m8n8.x4.shared.b16 {%0,%1,%2,%3}, [%4];"
                 : "=r"(r0), "=r"(r1), "=r"(r2), "=r"(r3) : "r"(addr));
}
__device__ __forceinline__ void ldsm_x2(uint32_t& r0, uint32_t& r1, uint32_t addr) {
    asm volatile("ldmatrix.sync.aligned.m8n8.x2.shared.b16 {%0,%1}, [%2];"
                 : "=r"(r0), "=r"(r1) : "r"(addr));
}
__device__ __forceinline__ void cp16(uint32_t dst, const void* src) {
    asm volatile("cp.async.ca.shared.global [%0], [%1], 16;\n" :: "r"(dst), "l"(src));
}
__device__ __forceinline__ void warp_argmax(float& v, int& i) {
    #pragma unroll
    for (int o = 16; o; o >>= 1) {
        float ov = __shfl_xor_sync(0xffffffffu, v, o);
        int   oi = __shfl_xor_sync(0xffffffffu, i, o);
        if (ov > v || (ov == v && oi < i)) { v = ov; i = oi; }
    }
}
__device__ __forceinline__ float warp_sum(float v) {
    #pragma unroll
    for (int o = 16; o; o >>= 1) v += __shfl_xor_sync(0xffffffffu, v, o);
    return v;
}
__device__ __forceinline__ uint32_t as_u32(__nv_bfloat162 h) {
    return *reinterpret_cast<uint32_t*>(&h);
}

// ---------------- main fused kernel: 2 CTAs/SM ----------------
__global__ void __launch_bounds__(NTHREADS, 2)
fused_kernel(const float* __restrict__ X,
             const float* __restrict__ cb1,
             const float* __restrict__ cw2,
             const float* __restrict__ cb2,
             const float* __restrict__ sw1,
             const float* __restrict__ sb1,
             const float* __restrict__ sw2,
             const float* __restrict__ sb2,
             const float* __restrict__ dirs,
             const float* __restrict__ gamma,
             const float* __restrict__ beta,
             const float* __restrict__ oscale_p,
             float* __restrict__ out) {
    extern __shared__ char sm[];
    float* Csm  = (float*)sm;
    float* b1c  = (float*)(sm + PARAM_OFF);
    float* w2c0 = b1c + COMP_H;
    float* w2c1 = w2c0 + COMP_H;
    const uint32_t smem_u32 = (uint32_t)__cvta_generic_to_shared(sm);

    const int tid  = threadIdx.x;
    const int lane = tid & 31;
    const int wid  = tid >> 5;      // 0..7
    const int mw   = wid & 1;       // m16 subtile (2)
    const int nw   = wid >> 1;      // 0..3, 11 n8-tiles each
    const int r0   = blockIdx.x * M_BLK;

    if (tid < COMP_H) {
        b1c[tid]  = cb1[tid];
        w2c0[tid] = cw2[tid * 2 + 0];
        w2c1[tid] = cw2[tid * 2 + 1];
    }
    const float oscale = oscale_p[0];
    const float b2_0 = cb2[0];
    const float b2_1 = cb2[1];

    float acc[NT_PER][4];
    #pragma unroll
    for (int t = 0; t < NT_PER; ++t)
        #pragma unroll
        for (int j = 0; j < 4; ++j) acc[t][j] = 0.f;

    const float4* X4 = (const float4*)X;
    const int arow = tid >> 2, aq = tid & 3;      // A-fill mapping (threads < 128)
    const bool afill = (tid < 128);

    // per-warp ldmatrix offsets (within a stage)
    const uint32_t a_lm_off  = (uint32_t)((mw * 16 + (lane & 15)) * ROWB + (lane >> 4) * 16);
    const uint32_t b_lm_off4 = (uint32_t)((((lane >> 4) & 1) * 8 + (lane & 7)) * ROWB
                                          + ((lane >> 3) & 1) * 16);
    const uint32_t b_lm_off2 = (uint32_t)(((lane & 7)) * ROWB + (((lane >> 3) & 1)) * 16);

    auto fill_B = [&](int kc, int stage) {
        const char* src = (const char*)&g_Wcat[kc][0][0];
        uint32_t bb = smem_u32 + stage * STAGE_BYTES + A_BYTES;
        #pragma unroll
        for (int rep = 0; rep < 6; ++rep) {
            int s = tid + rep * NTHREADS;
            if (s < B_SEGS)
                cp16(bb + (s >> 2) * ROWB + (s & 3) * 16, src + s * 16);
        }
        asm volatile("cp.async.commit_group;\n");
    };
    auto store_A = [&](const float4& v0, const float4& v1, int stage) {
        uint4 hh = make_uint4(as_u32(__floats2bfloat162_rn(v0.x, v0.y)),
                              as_u32(__floats2bfloat162_rn(v0.z, v0.w)),
                              as_u32(__floats2bfloat162_rn(v1.x, v1.y)),
                              as_u32(__floats2bfloat162_rn(v1.z, v1.w)));
        *(uint4*)(sm + stage * STAGE_BYTES + arow * ROWB + aq * 16) = hh;
    };

    // ---- prologue: stage 0 <- chunk 0 ----
    {
        fill_B(0, 0);
        if (afill) {
            const float4* p = X4 + (size_t)(r0 + arow) * (D_MODEL / 4) + aq * 2;
            float4 v0 = p[0], v1 = p[1];
            store_A(v0, v1, 0);
        }
        asm volatile("cp.async.wait_group 0;\n");
        __syncthreads();
    }

    // ---- pipelined mainloop ----
    for (int kc = 0; kc < NCHUNK; ++kc) {
        const int cur = kc & 1, nxt = cur ^ 1;
        const bool has_next = (kc + 1 < NCHUNK);
        const uint32_t sb = smem_u32 + cur * STAGE_BYTES;

        float4 v0, v1;
        if (has_next) {
            if (afill) {
                const float4* p = X4 + (size_t)(r0 + arow) * (D_MODEL / 4)
                                  + (kc + 1) * (KC / 4) + aq * 2;
                v0 = p[0]; v1 = p[1];
            }
            fill_B(kc + 1, nxt);
        }

        // MMAs on current stage (software-pipelined B ldmatrix)
        #pragma unroll
        for (int ks = 0; ks < 2; ++ks) {
            uint32_t a0, a1, a2, a3;
            ldsm_x4(a0, a1, a2, a3, sb + a_lm_off + ks * 32);
            const uint32_t bbase = sb + A_BYTES + (uint32_t)(nw * NT_PER * 8 * ROWB) + ks * 32;
            uint32_t p0, p1, p2, p3;
            ldsm_x4(p0, p1, p2, p3, bbase + b_lm_off4);
            #pragma unroll
            for (int p = 0; p < 4; ++p) {
                uint32_t q0, q1, q2, q3;
                ldsm_x4(q0, q1, q2, q3, bbase + b_lm_off4 + (uint32_t)((p + 1) * 16 * ROWB));
                mma16816(acc[2 * p],     a0, a1, a2, a3, p0, p1);
                mma16816(acc[2 * p + 1], a0, a1, a2, a3, p2, p3);
                p0 = q0; p1 = q1; p2 = q2; p3 = q3;
            }
            uint32_t t0, t1;
            ldsm_x2(t0, t1, bbase + b_lm_off2 + (uint32_t)(10 * 8 * ROWB));
            mma16816(acc[8], a0, a1, a2, a3, p0, p1);
            mma16816(acc[9], a0, a1, a2, a3, p2, p3);
            mma16816(acc[10], a0, a1, a2, a3, t0, t1);
        }

        if (has_next && afill) store_A(v0, v1, nxt);
        asm volatile("cp.async.wait_group 0;\n");
        __syncthreads();
    }

    // ---- dump C to smem (stages dead now) ----
    #pragma unroll
    for (int nt = 0; nt < NT_PER; ++nt) {
        int nb = (nw * NT_PER + nt) * 8;
        int cr = mw * 16 + (lane >> 2);
        int cc = nb + (lane & 3) * 2;
        *(float2*)&Csm[cr * CSTRIDE + cc]       = make_float2(acc[nt][0], acc[nt][1]);
        *(float2*)&Csm[(cr + 8) * CSTRIDE + cc] = make_float2(acc[nt][2], acc[nt][3]);
    }
    __syncthreads();

    // ---- epilogue: one warp per token, 4 tokens per warp ----
    for (int it = 0; it < 4; ++it) {
        const int m = wid * 4 + it;
        const int r = r0 + m;
        const float* crow = Csm + m * CSTRIDE;

        float s0 = 0.f, s1 = 0.f;
        #pragma unroll
        for (int jj = 0; jj < 8; ++jj) {
            int j = lane + jj * 32;
            float h = gelu_exact(crow[j] + b1c[j]);
            s0 += h * w2c0[j];
            s1 += h * w2c1[j];
        }
        s0 = warp_sum(s0);
        s1 = warp_sum(s1);
        float comp0 = tanhf(s0 + b2_0);
        float comp1 = tanhf(s1 + b2_1);

        // routing (calibration monotone -> argmax of raw scores)
        float cv = -INFINITY; int ci = 1 << 20;
        if (lane < NUM_CL) { cv = crow[COMP_H + lane]; ci = lane; }
        warp_argmax(cv, ci);
        float tv = -INFINITY; int tl = 1 << 20;
        if (lane < TPC) { tv = crow[COMP_H + NUM_CL + ci * TPC + lane]; tl = lane; }
        warp_argmax(tv, tl);
        const int tile = ci * TPC + tl;

        // tiny spline MLP
        float contrib = 0.f;
        if (lane < GRIDW) {
            int g = lane;
            float hw = comp0 * sw1[tile * 32 + g] + comp1 * sw1[tile * 32 + 16 + g]
                       + sb1[tile * 16 + g];
            hw = fmaxf(hw, 0.f);
            contrib = hw * sw2[tile * 16 + g];
        }
        float mag = warp_sum(contrib) + sb2[tile];
        const float factor = mag * oscale;

        // residual + layernorm (fp32 exact)
        const float* xr = X + (size_t)r * D_MODEL;
        const float* dr = dirs + (size_t)tile * D_MODEL;
        float f[32];
        float sum = 0.f, sumsq = 0.f;
        #pragma unroll
        for (int ii = 0; ii < 32; ++ii) {
            int i = lane + ii * 32;
            float y = xr[i] + factor * dr[i];
            f[ii] = y;
            sum += y;
            sumsq += y * y;
        }
        sum   = warp_sum(sum);
        sumsq = warp_sum(sumsq);
        const float mu   = sum * (1.f / D_MODEL);
        const float var  = sumsq * (1.f / D_MODEL) - mu * mu;
        const float rstd = rsqrtf(var + EPS_LN);
        float* orow = out + (size_t)r * D_MODEL;
        #pragma unroll
        for (int ii = 0; ii < 32; ++ii) {
            int i = lane + ii * 32;
            orow[i] = (f[ii] - mu) * rstd * gamma[i] + beta[i];
        }
    }
}

// ---------------- launch ----------------
extern "C" void kernel_launch(void* const* d_in, const int* in_sizes, int n_in,
                              void* d_out, int out_size) {
    const float* x      = (const float*)d_in[0];
    const float* sraw   = (const float*)d_in[1];
    // d_in[2] knot_values, d_in[3] temperature: unused (calibration monotone)
    const float* cw1    = (const float*)d_in[4];
    const float* cb1    = (const float*)d_in[5];
    const float* cw2    = (const float*)d_in[6];
    const float* cb2    = (const float*)d_in[7];
    const float* sw1    = (const float*)d_in[8];
    const float* sb1    = (const float*)d_in[9];
    const float* sw2    = (const float*)d_in[10];
    const float* sb2    = (const float*)d_in[11];
    const float* dirs   = (const float*)d_in[12];
    const float* gamma  = (const float*)d_in[13];
    const float* beta   = (const float*)d_in[14];
    const float* oscale = (const float*)d_in[15];
    float* out = (float*)d_out;

    const int N = in_sizes[0] / D_MODEL;     // 16384
    const int nblocks = N / M_BLK;           // 512

    cudaFuncSetAttribute(fused_kernel,
                         cudaFuncAttributeMaxDynamicSharedMemorySize, SMEM_TOTAL);

    prep_w1<<<D_MODEL / 32, 256>>>(cw1);
    prep_sig<<<((NCOL_PAD - COMP_H) * D_MODEL + 255) / 256, 256>>>(sraw);
    fused_kernel<<<nblocks, NTHREADS, SMEM_TOTAL>>>(
        x, cb1, cw2, cb2, sw1, sb1, sw2, sb2, dirs, gamma, beta, oscale, out);
}

// round 11
// speedup vs baseline: 1.3319x; 1.3319x over previous
#include <cuda_runtime.h>
#include <cuda_bf16.h>
#include <cstdint>
#include <math.h>

// ---------------- problem constants ----------------
#define D_MODEL   1024
#define NUM_TILES 64
#define TPC       8
#define NUM_CL    8
#define COMP_H    256
#define GRIDW     16
#define EPS_LN    1e-5f

// ---------------- GEMM config ----------------
#define NCOL_PAD  384              // 48 n8-tiles (256 hidden + 8 cluster + 64 tile + 56 pad)
#define M_BLK     64
#define KC        64
#define NCHUNK    (D_MODEL / KC)   // 16
#define ROWB      144              // 128B k-data + 16B pad; ldmatrix conflict-free (9 mod 8 = 1)
#define CSTRIDE   388              // /4 for float2 align; row shift 4 banks
#define NTHREADS  512

#define A_BYTES      (M_BLK * ROWB)           // 9216
#define B_BYTES      (NCOL_PAD * ROWB)        // 55296
#define STAGE_BYTES  (A_BYTES + B_BYTES)      // 64512
#define B_SEGS       (NCOL_PAD * 8)           // 3072 16B-segs per chunk
#define PARAM_OFF    (2 * STAGE_BYTES)        // 129024 (Csm 99328 aliases stages)
#define SMEM_TOTAL   (PARAM_OFF + 3 * COMP_H * 4)   // 132096

// Wcat, chunk-major: [chunk][row n][k within chunk]
__device__ __nv_bfloat16 g_Wcat[NCHUNK][NCOL_PAD][KC];

// ---------------- merged prep: W1 transpose + signatures + pad --------------
// blocks 0..255: 32x32 tile transpose of compress_w1 [D,H] -> Wcat rows 0..255
// blocks 256..383: one n-row each (cluster sigs / tile sigs / zero pad)
__global__ void prep_kernel(const float* __restrict__ w1,
                            const float* __restrict__ raw) {
    __shared__ float t[32][33];
    const int b = blockIdx.x;
    if (b < 256) {
        const int tx = threadIdx.x & 31, ty = threadIdx.x >> 5;   // 32 x 8
        const int n0 = (b & 7) * 32, k0 = (b >> 3) * 32;
        #pragma unroll
        for (int r = 0; r < 4; ++r) {
            int k = k0 + ty + r * 8;
            t[ty + r * 8][tx] = w1[(size_t)k * COMP_H + n0 + tx];
        }
        __syncthreads();
        #pragma unroll
        for (int r = 0; r < 4; ++r) {
            int n = n0 + ty + r * 8;
            int k = k0 + tx;
            g_Wcat[k >> 6][n][k & 63] = __float2bfloat16(t[tx][ty + r * 8]);
        }
    } else {
        const int nn = b - 256;          // 0..127 -> n = 256..383
        const int n = COMP_H + nn;
        #pragma unroll
        for (int r = 0; r < 4; ++r) {
            int k = threadIdx.x + r * 256;
            float val;
            if (nn < NUM_CL) {
                float s = 0.f;
                #pragma unroll
                for (int j = 0; j < TPC; ++j) {
                    float rv = raw[(size_t)(nn * TPC + j) * D_MODEL + k];
                    s += (rv > 0.3f) ? 1.f : ((rv < -0.3f) ? -1.f : 0.f);
                }
                val = (s > 0.f) ? 1.f : ((s < 0.f) ? -1.f : 0.f);
            } else if (nn < NUM_CL + NUM_TILES) {
                float rv = raw[(size_t)(nn - NUM_CL) * D_MODEL + k];
                val = (rv > 0.3f) ? 1.f : ((rv < -0.3f) ? -1.f : 0.f);
            } else {
                val = 0.f;
            }
            g_Wcat[k >> 6][n][k & 63] = __float2bfloat16(val);
        }
    }
}

// ---------------- helpers ----------------
__device__ __forceinline__ float gelu_exact(float v) {
    return 0.5f * v * (1.0f + erff(v * 0.7071067811865476f));
}
__device__ __forceinline__ void mma16816(float c[4], uint32_t a0, uint32_t a1,
                                         uint32_t a2, uint32_t a3,
                                         uint32_t b0, uint32_t b1) {
    asm volatile(
        "mma.sync.aligned.m16n8k16.row.col.f32.bf16.bf16.f32 "
        "{%0,%1,%2,%3}, {%4,%5,%6,%7}, {%8,%9}, {%0,%1,%2,%3};\n"
        : "+f"(c[0]), "+f"(c[1]), "+f"(c[2]), "+f"(c[3])
        : "r"(a0), "r"(a1), "r"(a2), "r"(a3), "r"(b0), "r"(b1));
}
__device__ __forceinline__ void ldsm_x4(uint32_t& r0, uint32_t& r1, uint32_t& r2,
                                        uint32_t& r3, uint32_t addr) {
    asm volatile("ldmatrix.sync.aligned.m8n8.x4.shared.b16 {%0,%1,%2,%3}, [%4];"
                 : "=r"(r0), "=r"(r1), "=r"(r2), "=r"(r3) : "r"(addr));
}
__device__ __forceinline__ void cp16(uint32_t dst, const void* src) {
    asm volatile("cp.async.ca.shared.global [%0], [%1], 16;\n" :: "r"(dst), "l"(src));
}
__device__ __forceinline__ void warp_argmax(float& v, int& i) {
    #pragma unroll
    for (int o = 16; o; o >>= 1) {
        float ov = __shfl_xor_sync(0xffffffffu, v, o);
        int   oi = __shfl_xor_sync(0xffffffffu, i, o);
        if (ov > v || (ov == v && oi < i)) { v = ov; i = oi; }
    }
}
__device__ __forceinline__ float warp_sum(float v) {
    #pragma unroll
    for (int o = 16; o; o >>= 1) v += __shfl_xor_sync(0xffffffffu, v, o);
    return v;
}
__device__ __forceinline__ uint32_t as_u32(__nv_bfloat162 h) {
    return *reinterpret_cast<uint32_t*>(&h);
}

// ---------------- main fused kernel ----------------
__global__ void __launch_bounds__(NTHREADS)
fused_kernel(const float* __restrict__ X,
             const float* __restrict__ cb1,
             const float* __restrict__ cw2,
             const float* __restrict__ cb2,
             const float* __restrict__ sw1,
             const float* __restrict__ sb1,
             const float* __restrict__ sw2,
             const float* __restrict__ sb2,
             const float* __restrict__ dirs,
             const float* __restrict__ gamma,
             const float* __restrict__ beta,
             const float* __restrict__ oscale_p,
             float* __restrict__ out) {
    extern __shared__ char sm[];
    float* Csm  = (float*)sm;
    float* b1c  = (float*)(sm + PARAM_OFF);
    float* w2c0 = b1c + COMP_H;
    float* w2c1 = w2c0 + COMP_H;
    const uint32_t smem_u32 = (uint32_t)__cvta_generic_to_shared(sm);

    const int tid  = threadIdx.x;
    const int lane = tid & 31;
    const int wid  = tid >> 5;      // 0..15
    const int mw   = wid & 1;       // 2 m-groups of 32 rows
    const int nw   = wid >> 1;      // 8 n-groups of 48 cols (6 n8-tiles)
    const int r0   = blockIdx.x * M_BLK;

    if (tid < COMP_H) {
        b1c[tid]  = cb1[tid];
        w2c0[tid] = cw2[tid * 2 + 0];
        w2c1[tid] = cw2[tid * 2 + 1];
    }
    const float oscale = oscale_p[0];
    const float b2_0 = cb2[0];
    const float b2_1 = cb2[1];

    float acc[2][6][4];
    #pragma unroll
    for (int mt = 0; mt < 2; ++mt)
        #pragma unroll
        for (int nt = 0; nt < 6; ++nt)
            #pragma unroll
            for (int j = 0; j < 4; ++j) acc[mt][nt][j] = 0.f;

    const float4* X4 = (const float4*)X;
    const int arow = tid >> 3, asg = tid & 7;      // A-fill: 512 segs of 16B

    // per-warp ldmatrix offsets (within a stage)
    const uint32_t a_lm0 = (uint32_t)((mw * 32 + (lane & 15)) * ROWB + (lane >> 4) * 16);
    const uint32_t a_lm1 = a_lm0 + 16u * ROWB;
    const uint32_t b_lm4 = (uint32_t)((((lane >> 4) & 1) * 8 + (lane & 7)) * ROWB
                                      + ((lane >> 3) & 1) * 16);

    auto fill_B = [&](int kc, int stage) {
        const char* src = (const char*)&g_Wcat[kc][0][0];
        uint32_t bb = smem_u32 + stage * STAGE_BYTES + A_BYTES;
        #pragma unroll
        for (int rep = 0; rep < 6; ++rep) {
            int s = tid + rep * NTHREADS;        // exactly B_SEGS = 3072
            cp16(bb + (s >> 3) * ROWB + (s & 7) * 16, src + s * 16);
        }
        asm volatile("cp.async.commit_group;\n");
    };
    auto store_A = [&](const float4& v0, const float4& v1, int stage) {
        uint4 hh = make_uint4(as_u32(__floats2bfloat162_rn(v0.x, v0.y)),
                              as_u32(__floats2bfloat162_rn(v0.z, v0.w)),
                              as_u32(__floats2bfloat162_rn(v1.x, v1.y)),
                              as_u32(__floats2bfloat162_rn(v1.z, v1.w)));
        *(uint4*)(sm + stage * STAGE_BYTES + arow * ROWB + asg * 16) = hh;
    };

    // ---- prologue: stage 0 <- chunk 0 ----
    {
        fill_B(0, 0);
        const float4* p = X4 + (size_t)(r0 + arow) * (D_MODEL / 4) + asg * 2;
        float4 v0 = p[0], v1 = p[1];
        store_A(v0, v1, 0);
        asm volatile("cp.async.wait_group 0;\n");
        __syncthreads();
    }

    // ---- pipelined mainloop ----
    for (int kc = 0; kc < NCHUNK; ++kc) {
        const int cur = kc & 1, nxt = cur ^ 1;
        const bool has_next = (kc + 1 < NCHUNK);
        const uint32_t sb = smem_u32 + cur * STAGE_BYTES;

        float4 v0, v1;
        if (has_next) {
            const float4* p = X4 + (size_t)(r0 + arow) * (D_MODEL / 4)
                              + (kc + 1) * (KC / 4) + asg * 2;
            v0 = p[0]; v1 = p[1];
            fill_B(kc + 1, nxt);
        }

        // MMAs on current stage: warp tile m32 x n48
        #pragma unroll
        for (int ks = 0; ks < 4; ++ks) {
            uint32_t a0[4], a1[4];
            ldsm_x4(a0[0], a0[1], a0[2], a0[3], sb + a_lm0 + ks * 32);
            ldsm_x4(a1[0], a1[1], a1[2], a1[3], sb + a_lm1 + ks * 32);
            const uint32_t bbase = sb + A_BYTES + (uint32_t)(nw * 48 * ROWB) + ks * 32;
            uint32_t p0, p1, p2, p3;
            ldsm_x4(p0, p1, p2, p3, bbase + b_lm4);
            #pragma unroll
            for (int p = 0; p < 3; ++p) {
                uint32_t q0, q1, q2, q3;
                if (p < 2)
                    ldsm_x4(q0, q1, q2, q3, bbase + b_lm4 + (uint32_t)((p + 1) * 16 * ROWB));
                mma16816(acc[0][2 * p],     a0[0], a0[1], a0[2], a0[3], p0, p1);
                mma16816(acc[1][2 * p],     a1[0], a1[1], a1[2], a1[3], p0, p1);
                mma16816(acc[0][2 * p + 1], a0[0], a0[1], a0[2], a0[3], p2, p3);
                mma16816(acc[1][2 * p + 1], a1[0], a1[1], a1[2], a1[3], p2, p3);
                p0 = q0; p1 = q1; p2 = q2; p3 = q3;
            }
        }

        if (has_next) store_A(v0, v1, nxt);
        asm volatile("cp.async.wait_group 0;\n");
        __syncthreads();
    }

    // ---- dump C to smem (stages dead now) ----
    #pragma unroll
    for (int mt = 0; mt < 2; ++mt)
        #pragma unroll
        for (int nt = 0; nt < 6; ++nt) {
            int cr = mw * 32 + mt * 16 + (lane >> 2);
            int cc = (nw * 6 + nt) * 8 + (lane & 3) * 2;
            *(float2*)&Csm[cr * CSTRIDE + cc] =
                make_float2(acc[mt][nt][0], acc[mt][nt][1]);
            *(float2*)&Csm[(cr + 8) * CSTRIDE + cc] =
                make_float2(acc[mt][nt][2], acc[mt][nt][3]);
        }
    __syncthreads();

    // ---- epilogue: one warp per token, 4 tokens per warp ----
    for (int it = 0; it < 4; ++it) {
        const int m = wid * 4 + it;
        const int r = r0 + m;
        const float* crow = Csm + m * CSTRIDE;

        float s0 = 0.f, s1 = 0.f;
        #pragma unroll
        for (int jj = 0; jj < 8; ++jj) {
            int j = lane + jj * 32;
            float h = gelu_exact(crow[j] + b1c[j]);
            s0 += h * w2c0[j];
            s1 += h * w2c1[j];
        }
        s0 = warp_sum(s0);
        s1 = warp_sum(s1);
        float comp0 = tanhf(s0 + b2_0);
        float comp1 = tanhf(s1 + b2_1);

        // routing (calibration monotone -> argmax of raw scores)
        float cv = -INFINITY; int ci = 1 << 20;
        if (lane < NUM_CL) { cv = crow[COMP_H + lane]; ci = lane; }
        warp_argmax(cv, ci);
        float tv = -INFINITY; int tl = 1 << 20;
        if (lane < TPC) { tv = crow[COMP_H + NUM_CL + ci * TPC + lane]; tl = lane; }
        warp_argmax(tv, tl);
        const int tile = ci * TPC + tl;

        // tiny spline MLP
        float contrib = 0.f;
        if (lane < GRIDW) {
            int g = lane;
            float hw = comp0 * sw1[tile * 32 + g] + comp1 * sw1[tile * 32 + 16 + g]
                       + sb1[tile * 16 + g];
            hw = fmaxf(hw, 0.f);
            contrib = hw * sw2[tile * 16 + g];
        }
        float mag = warp_sum(contrib) + sb2[tile];
        const float factor = mag * oscale;

        // residual + layernorm (fp32 exact, float4 vectorized)
        const float4* xr4 = (const float4*)(X + (size_t)r * D_MODEL);
        const float4* dr4 = (const float4*)(dirs + (size_t)tile * D_MODEL);
        const float4* g4  = (const float4*)gamma;
        const float4* be4 = (const float4*)beta;
        float4* o4 = (float4*)(out + (size_t)r * D_MODEL);
        float4 f4[8];
        float sum = 0.f, sumsq = 0.f;
        #pragma unroll
        for (int ii = 0; ii < 8; ++ii) {
            int i = lane + ii * 32;
            float4 xv = xr4[i], dv = dr4[i];
            float4 y;
            y.x = xv.x + factor * dv.x;
            y.y = xv.y + factor * dv.y;
            y.z = xv.z + factor * dv.z;
            y.w = xv.w + factor * dv.w;
            f4[ii] = y;
            sum   += y.x + y.y + y.z + y.w;
            sumsq += y.x * y.x + y.y * y.y + y.z * y.z + y.w * y.w;
        }
        sum   = warp_sum(sum);
        sumsq = warp_sum(sumsq);
        const float mu   = sum * (1.f / D_MODEL);
        const float var  = sumsq * (1.f / D_MODEL) - mu * mu;
        const float rstd = rsqrtf(var + EPS_LN);
        #pragma unroll
        for (int ii = 0; ii < 8; ++ii) {
            int i = lane + ii * 32;
            float4 gv = g4[i], bv = be4[i], y = f4[ii], o;
            o.x = (y.x - mu) * rstd * gv.x + bv.x;
            o.y = (y.y - mu) * rstd * gv.y + bv.y;
            o.z = (y.z - mu) * rstd * gv.z + bv.z;
            o.w = (y.w - mu) * rstd * gv.w + bv.w;
            o4[i] = o;
        }
    }
}

// ---------------- launch ----------------
extern "C" void kernel_launch(void* const* d_in, const int* in_sizes, int n_in,
                              void* d_out, int out_size) {
    const float* x      = (const float*)d_in[0];
    const float* sraw   = (const float*)d_in[1];
    // d_in[2] knot_values, d_in[3] temperature: unused (calibration monotone)
    const float* cw1    = (const float*)d_in[4];
    const float* cb1    = (const float*)d_in[5];
    const float* cw2    = (const float*)d_in[6];
    const float* cb2    = (const float*)d_in[7];
    const float* sw1    = (const float*)d_in[8];
    const float* sb1    = (const float*)d_in[9];
    const float* sw2    = (const float*)d_in[10];
    const float* sb2    = (const float*)d_in[11];
    const float* dirs   = (const float*)d_in[12];
    const float* gamma  = (const float*)d_in[13];
    const float* beta   = (const float*)d_in[14];
    const float* oscale = (const float*)d_in[15];
    float* out = (float*)d_out;

    const int N = in_sizes[0] / D_MODEL;     // 16384
    const int nblocks = N / M_BLK;           // 256

    cudaFuncSetAttribute(fused_kernel,
                         cudaFuncAttributeMaxDynamicSharedMemorySize, SMEM_TOTAL);

    prep_kernel<<<384, 256>>>(cw1, sraw);
    fused_kernel<<<nblocks, NTHREADS, SMEM_TOTAL>>>(
        x, cb1, cw2, cb2, sw1, sb1, sw2, sb2, dirs, gamma, beta, oscale, out);
}